// round 2
// baseline (speedup 1.0000x reference)
#include <cuda_runtime.h>
#include <cfloat>
#include <cstddef>

#define B 64
#define TIN 256
#define F 64
#define H 1024
#define H3 3072
#define TGT 64
#define V 32000
#define BH (B*H)

// ---------------- device-global scratch (no allocation allowed) ----------------
__device__ float g_gi0[(size_t)TIN * B * H3];   // rows (b*TIN + t), 3H wide
__device__ float g_gi1[(size_t)TIN * B * H3];   // rows (t*B + b), 3H wide
__device__ float g_h0seq[(size_t)TIN * BH];     // [t][b][H]
__device__ float g_enc[(size_t)TIN * BH];       // [t][b][H]
__device__ float g_dh0[2 * BH];
__device__ float g_dh1[2 * BH];
__device__ float g_q[BH];
__device__ float g_cat[B * 2 * H];              // [b][0:H]=att, [b][H:2H]=h1
__device__ float g_comb[BH];
__device__ int   g_tok[B];
__device__ unsigned long long g_bar64;          // low32 = count, high32 = generation

__device__ __forceinline__ void grid_sync() {
    __syncthreads();
    if (threadIdx.x == 0) {
        __threadfence();
        unsigned long long old = atomicAdd(&g_bar64, 1ULL);
        unsigned gen = (unsigned)(old >> 32);
        if ((unsigned)old == gridDim.x - 1) {
            // last arriver: reset count to 0 and bump generation atomically
            atomicAdd(&g_bar64, (1ULL << 32) - (unsigned long long)gridDim.x);
        } else {
            while ((unsigned)((*(volatile unsigned long long*)&g_bar64) >> 32) == gen) { }
        }
        __threadfence();
    }
    __syncthreads();
}

__device__ __forceinline__ float sigmoidf_(float x) { return 1.f / (1.f + expf(-x)); }

// ---------------- generic GEMM: C[M,N] = A[M,K] @ W[N,K]^T + bias ----------------
template<int BM, int BN, int BK, int TM, int TN>
__global__ void gemm_tn(const float* __restrict__ A, const float* __restrict__ Wt,
                        const float* __restrict__ bias, float* __restrict__ C,
                        int M, int N, int K, int lda, int ldw, int ldc) {
    constexpr int TX = BN / TN;
    constexpr int TY = BM / TM;
    constexpr int NT = TX * TY;
    __shared__ float As[BK][BM + 1];
    __shared__ float Ws[BK][BN + 1];
    const int tid = threadIdx.x;
    const int tx = tid % TX, ty = tid / TX;
    const int m0 = blockIdx.y * BM, n0 = blockIdx.x * BN;

    float acc[TM][TN];
#pragma unroll
    for (int i = 0; i < TM; i++)
#pragma unroll
        for (int j = 0; j < TN; j++) acc[i][j] = 0.f;

    for (int k0 = 0; k0 < K; k0 += BK) {
        for (int i = tid; i < BM * BK; i += NT) {
            int m = i / BK, k = i % BK;
            As[k][m] = A[(size_t)(m0 + m) * lda + k0 + k];
        }
        for (int i = tid; i < BN * BK; i += NT) {
            int n = i / BK, k = i % BK;
            Ws[k][n] = Wt[(size_t)(n0 + n) * ldw + k0 + k];
        }
        __syncthreads();
#pragma unroll
        for (int k = 0; k < BK; k++) {
            float a[TM], w[TN];
#pragma unroll
            for (int i = 0; i < TM; i++) a[i] = As[k][ty + i * TY];
#pragma unroll
            for (int j = 0; j < TN; j++) w[j] = Ws[k][tx + j * TX];
#pragma unroll
            for (int i = 0; i < TM; i++)
#pragma unroll
                for (int j = 0; j < TN; j++) acc[i][j] = fmaf(a[i], w[j], acc[i][j]);
        }
        __syncthreads();
    }
#pragma unroll
    for (int i = 0; i < TM; i++) {
        int m = m0 + ty + i * TY;
#pragma unroll
        for (int j = 0; j < TN; j++) {
            int n = n0 + tx + j * TX;
            C[(size_t)m * ldc + n] = acc[i][j] + (bias ? bias[n] : 0.f);
        }
    }
}

// ---------------- persistent encoder recurrence (one layer, all 256 steps) ----------------
// grid = 128 blocks x 256 threads. Block owns 8 output cols; Whh slice (24 rows x 1024)
// held in smem for the whole kernel. Grid-sync per timestep.
#define WS_PITCH 1028
#define XS_PITCH 68
__global__ __launch_bounds__(256, 1) void enc_recur_kernel(
    const float* __restrict__ gi, long long gi_t_stride, long long gi_b_stride,
    const float* __restrict__ Whh, const float* __restrict__ bhh,
    float* __restrict__ hseq)
{
    extern __shared__ float sm[];
    float* ws = sm;                      // 24 x WS_PITCH
    float* xs = sm + 24 * WS_PITCH;      // 64 x XS_PITCH

    const int tid = threadIdx.x;
    const int c = tid & 7, bq = tid >> 3;
    const int jb = blockIdx.x * 8;
    const int b0 = 2 * bq, b1 = b0 + 1;
    const int j = jb + c;

    // preload Whh rows (r, z, n gates for our 8 columns), full K
    for (int i = tid; i < 24 * 256; i += 256) {
        int r = i >> 8, kg = i & 255;
        int wr = (r >> 3) * H + jb + (r & 7);
        *(float4*)(ws + r * WS_PITCH + kg * 4) =
            *(const float4*)(Whh + (size_t)wr * H + kg * 4);
    }
    const float br = bhh[j], bz = bhh[H + j], bn = bhh[2 * H + j];
    __syncthreads();

    for (int t = 0; t < TIN; t++) {
        float ar0 = 0.f, ar1 = 0.f, az0 = 0.f, az1 = 0.f, an0 = 0.f, an1 = 0.f;
        const float* hprev = hseq + (size_t)(t - 1) * BH;
        if (t > 0) {
            for (int k0 = 0; k0 < H; k0 += 64) {
                for (int i = tid; i < 1024; i += 256) {
                    int b = i >> 4, kg = i & 15;
                    *(float4*)(xs + b * XS_PITCH + kg * 4) =
                        *(const float4*)(hprev + (size_t)b * H + k0 + kg * 4);
                }
                __syncthreads();
#pragma unroll
                for (int kk = 0; kk < 64; kk += 4) {
                    float4 x0 = *(const float4*)(xs + b0 * XS_PITCH + kk);
                    float4 x1 = *(const float4*)(xs + b1 * XS_PITCH + kk);
                    float4 w0 = *(const float4*)(ws + c * WS_PITCH + k0 + kk);
                    float4 w1 = *(const float4*)(ws + (8 + c) * WS_PITCH + k0 + kk);
                    float4 w2 = *(const float4*)(ws + (16 + c) * WS_PITCH + k0 + kk);
                    ar0 = fmaf(w0.x, x0.x, ar0); ar0 = fmaf(w0.y, x0.y, ar0);
                    ar0 = fmaf(w0.z, x0.z, ar0); ar0 = fmaf(w0.w, x0.w, ar0);
                    ar1 = fmaf(w0.x, x1.x, ar1); ar1 = fmaf(w0.y, x1.y, ar1);
                    ar1 = fmaf(w0.z, x1.z, ar1); ar1 = fmaf(w0.w, x1.w, ar1);
                    az0 = fmaf(w1.x, x0.x, az0); az0 = fmaf(w1.y, x0.y, az0);
                    az0 = fmaf(w1.z, x0.z, az0); az0 = fmaf(w1.w, x0.w, az0);
                    az1 = fmaf(w1.x, x1.x, az1); az1 = fmaf(w1.y, x1.y, az1);
                    az1 = fmaf(w1.z, x1.z, az1); az1 = fmaf(w1.w, x1.w, az1);
                    an0 = fmaf(w2.x, x0.x, an0); an0 = fmaf(w2.y, x0.y, an0);
                    an0 = fmaf(w2.z, x0.z, an0); an0 = fmaf(w2.w, x0.w, an0);
                    an1 = fmaf(w2.x, x1.x, an1); an1 = fmaf(w2.y, x1.y, an1);
                    an1 = fmaf(w2.z, x1.z, an1); an1 = fmaf(w2.w, x1.w, an1);
                }
                __syncthreads();
            }
        }
        // epilogue
        const float* gr0 = gi + (size_t)b0 * gi_b_stride + (size_t)t * gi_t_stride;
        const float* gr1 = gi + (size_t)b1 * gi_b_stride + (size_t)t * gi_t_stride;
        float* hout = hseq + (size_t)t * BH;
        float hp0 = (t > 0) ? hprev[(size_t)b0 * H + j] : 0.f;
        float hp1 = (t > 0) ? hprev[(size_t)b1 * H + j] : 0.f;
        {
            float r = sigmoidf_(gr0[j] + ar0 + br);
            float z = sigmoidf_(gr0[H + j] + az0 + bz);
            float n = tanhf(gr0[2 * H + j] + r * (an0 + bn));
            hout[(size_t)b0 * H + j] = (1.f - z) * n + z * hp0;
        }
        {
            float r = sigmoidf_(gr1[j] + ar1 + br);
            float z = sigmoidf_(gr1[H + j] + az1 + bz);
            float n = tanhf(gr1[2 * H + j] + r * (an1 + bn));
            hout[(size_t)b1 * H + j] = (1.f - z) * n + z * hp1;
        }
        grid_sync();
    }
}

// ---------------- decoder building block: block-level GEMM accumulate ----------------
// acc[g*2+u] += sum_k W[((g*H)+jb+c)*wstride + k] * X[row(b_u)][k]
template<int NG>
__device__ __forceinline__ void block_mm(
    const float* __restrict__ W, int wstride,
    const float* __restrict__ X, int xstride, const int* __restrict__ rowidx,
    int K, float* acc, float* sm)
{
    const int tid = threadIdx.x;
    const int c = tid & 7, bq = tid >> 3;
    const int jb = blockIdx.x * 8;
    const int b0 = 2 * bq, b1 = b0 + 1;
    float* ws = sm;                     // NG*8 x XS_PITCH
    float* xs = sm + NG * 8 * XS_PITCH; // 64 x XS_PITCH

    for (int k0 = 0; k0 < K; k0 += 64) {
        for (int i = tid; i < 1024; i += 256) {
            int b = i >> 4, kg = i & 15;
            int xr = rowidx ? rowidx[b] : b;
            *(float4*)(xs + b * XS_PITCH + kg * 4) =
                *(const float4*)(X + (size_t)xr * xstride + k0 + kg * 4);
        }
        for (int i = tid; i < NG * 8 * 16; i += 256) {
            int r = i >> 4, kg = i & 15;
            int wr = (r >> 3) * H + jb + (r & 7);
            *(float4*)(ws + r * XS_PITCH + kg * 4) =
                *(const float4*)(W + (size_t)wr * wstride + k0 + kg * 4);
        }
        __syncthreads();
#pragma unroll
        for (int kk = 0; kk < 64; kk += 4) {
            float4 x0 = *(const float4*)(xs + b0 * XS_PITCH + kk);
            float4 x1 = *(const float4*)(xs + b1 * XS_PITCH + kk);
#pragma unroll
            for (int g = 0; g < NG; g++) {
                float4 w = *(const float4*)(ws + (g * 8 + c) * XS_PITCH + kk);
                float a0 = acc[g * 2], a1 = acc[g * 2 + 1];
                a0 = fmaf(w.x, x0.x, a0); a0 = fmaf(w.y, x0.y, a0);
                a0 = fmaf(w.z, x0.z, a0); a0 = fmaf(w.w, x0.w, a0);
                a1 = fmaf(w.x, x1.x, a1); a1 = fmaf(w.y, x1.y, a1);
                a1 = fmaf(w.z, x1.z, a1); a1 = fmaf(w.w, x1.w, a1);
                acc[g * 2] = a0; acc[g * 2 + 1] = a1;
            }
        }
        __syncthreads();
    }
}

__device__ __forceinline__ void dec_gru_phase(
    const float* __restrict__ x, int xstride, const int* __restrict__ rowidx,
    const float* __restrict__ Wih, const float* __restrict__ bih,
    const float* __restrict__ hin,
    const float* __restrict__ Whh, const float* __restrict__ bhh,
    float* __restrict__ hout, float* __restrict__ cat_aux, float* sm)
{
    if (blockIdx.x < 128) {
        float ai[6] = {0,0,0,0,0,0}, ah[6] = {0,0,0,0,0,0};
        block_mm<3>(Wih, H, x, xstride, rowidx, H, ai, sm);
        block_mm<3>(Whh, H, hin, H, nullptr, H, ah, sm);
        const int tid = threadIdx.x, c = tid & 7, bq = tid >> 3;
        const int j = blockIdx.x * 8 + c;
        const float bir = bih[j], biz = bih[H + j], bin = bih[2 * H + j];
        const float bhr = bhh[j], bhz = bhh[H + j], bhn = bhh[2 * H + j];
#pragma unroll
        for (int u = 0; u < 2; u++) {
            int b = 2 * bq + u;
            float hp = hin[(size_t)b * H + j];
            float r = sigmoidf_((ai[u] + bir) + (ah[u] + bhr));
            float z = sigmoidf_((ai[2 + u] + biz) + (ah[2 + u] + bhz));
            float n = tanhf((ai[4 + u] + bin) + r * (ah[4 + u] + bhn));
            float h = (1.f - z) * n + z * hp;
            hout[(size_t)b * H + j] = h;
            if (cat_aux) cat_aux[(size_t)b * 2 * H + H + j] = h;
        }
    }
    grid_sync();
}

__device__ __forceinline__ void lin_phase(
    const float* __restrict__ Wt, int wstride, const float* __restrict__ bias,
    const float* __restrict__ X, int xstride, int K, float* __restrict__ Y, float* sm)
{
    if (blockIdx.x < 128) {
        float a[2] = {0, 0};
        block_mm<1>(Wt, wstride, X, xstride, nullptr, K, a, sm);
        const int tid = threadIdx.x, c = tid & 7, bq = tid >> 3;
        const int j = blockIdx.x * 8 + c;
#pragma unroll
        for (int u = 0; u < 2; u++) {
            int b = 2 * bq + u;
            Y[(size_t)b * H + j] = a[u] + bias[j];
        }
    }
    grid_sync();
}

__device__ __forceinline__ void attn_phase(
    const float* __restrict__ q, const float* __restrict__ enc,
    float* __restrict__ cat, float* __restrict__ attn_out, int s, float* sm)
{
    if (blockIdx.x < B) {
        const int b = blockIdx.x, tid = threadIdx.x;
        float* qs = sm;           // 1024
        float* wv = sm + 1024;    // 256
        float* red = sm + 1280;   // 256
        for (int i = tid; i < H; i += 256) qs[i] = q[(size_t)b * H + i];
        __syncthreads();
        const int warp = tid >> 5, lane = tid & 31;
        for (int t = warp; t < TIN; t += 8) {
            const float* e = enc + (size_t)(t * B + b) * H;
            float sacc = 0.f;
#pragma unroll 4
            for (int k = lane; k < H; k += 32) sacc = fmaf(qs[k], e[k], sacc);
            for (int o = 16; o; o >>= 1) sacc += __shfl_xor_sync(0xffffffffu, sacc, o);
            if (!lane) wv[t] = sacc;
        }
        __syncthreads();
        float v = wv[tid];
        red[tid] = v; __syncthreads();
        for (int st = 128; st; st >>= 1) { if (tid < st) red[tid] = fmaxf(red[tid], red[tid + st]); __syncthreads(); }
        float mx = red[0]; __syncthreads();
        float ev = expf(v - mx);
        red[tid] = ev; __syncthreads();
        for (int st = 128; st; st >>= 1) { if (tid < st) red[tid] += red[tid + st]; __syncthreads(); }
        float aw = ev / red[0];
        wv[tid] = aw;
        attn_out[((size_t)b * TIN + tid) * TGT + s] = aw;
        __syncthreads();
#pragma unroll
        for (int kk = 0; kk < 4; kk++) {
            int k = tid + kk * 256;
            float sacc = 0.f;
            for (int t = 0; t < TIN; t++) sacc = fmaf(wv[t], enc[(size_t)(t * B + b) * H + k], sacc);
            cat[(size_t)b * 2 * H + k] = sacc;
        }
    }
    grid_sync();
}

__device__ __forceinline__ void fc_phase(
    const float* __restrict__ A, const float* __restrict__ Wfc,
    const float* __restrict__ bfc, float* __restrict__ out, int s, float* sm)
{
    float* As = sm;             // 32 x 65
    float* Ws2 = sm + 32 * 65;  // 32 x 130
    const int tid = threadIdx.x;
    const int tx = tid & 15, ty = tid >> 4;
    for (int tile = blockIdx.x; tile < V / 128; tile += gridDim.x) {
        const int n0 = tile * 128;
        float acc[4][8];
#pragma unroll
        for (int i = 0; i < 4; i++)
#pragma unroll
            for (int jj = 0; jj < 8; jj++) acc[i][jj] = 0.f;
        for (int k0 = 0; k0 < H; k0 += 32) {
            for (int i = tid; i < 64 * 32; i += 256) {
                int m = i >> 5, k = i & 31;
                As[k * 65 + m] = A[(size_t)m * H + k0 + k];
            }
            for (int i = tid; i < 128 * 32; i += 256) {
                int n = i >> 5, k = i & 31;
                Ws2[k * 130 + n] = Wfc[(size_t)(n0 + n) * H + k0 + k];
            }
            __syncthreads();
#pragma unroll
            for (int k = 0; k < 32; k++) {
                float av[4], wv2[8];
#pragma unroll
                for (int i = 0; i < 4; i++) av[i] = As[k * 65 + ty + i * 16];
#pragma unroll
                for (int jj = 0; jj < 8; jj++) wv2[jj] = Ws2[k * 130 + tx + jj * 16];
#pragma unroll
                for (int i = 0; i < 4; i++)
#pragma unroll
                    for (int jj = 0; jj < 8; jj++) acc[i][jj] = fmaf(av[i], wv2[jj], acc[i][jj]);
            }
            __syncthreads();
        }
#pragma unroll
        for (int i = 0; i < 4; i++) {
            int m = ty + i * 16;
#pragma unroll
            for (int jj = 0; jj < 8; jj++) {
                int n = n0 + tx + jj * 16;
                out[((size_t)m * TGT + s) * V + n] = acc[i][jj] + bfc[n];
            }
        }
    }
    grid_sync();
}

__device__ __forceinline__ void argmax_phase(const float* __restrict__ out, int s, float* sm)
{
    if (blockIdx.x < B) {
        const int b = blockIdx.x, tid = threadIdx.x;
        const float* row = out + ((size_t)b * TGT + s) * V;
        float best = -FLT_MAX; int bi = 0;
        for (int i = tid; i < V; i += 256) {
            float x = row[i];
            if (x > best) { best = x; bi = i; }
        }
        float* sv = sm;
        int* si = (int*)(sm + 256);
        sv[tid] = best; si[tid] = bi; __syncthreads();
        for (int st = 128; st; st >>= 1) {
            if (tid < st) {
                if (sv[tid + st] > sv[tid] ||
                    (sv[tid + st] == sv[tid] && si[tid + st] < si[tid])) {
                    sv[tid] = sv[tid + st]; si[tid] = si[tid + st];
                }
            }
            __syncthreads();
        }
        if (!tid) g_tok[b] = si[0];
    }
    grid_sync();
}

// ---------------- persistent decoder: all 64 steps in one kernel ----------------
__global__ __launch_bounds__(256, 1) void decoder_kernel(
    const float* __restrict__ embed,
    const float* __restrict__ dWih0, const float* __restrict__ dbih0,
    const float* __restrict__ dWhh0, const float* __restrict__ dbhh0,
    const float* __restrict__ dWih1, const float* __restrict__ dbih1,
    const float* __restrict__ dWhh1, const float* __restrict__ dbhh1,
    const float* __restrict__ Wq, const float* __restrict__ bq,
    const float* __restrict__ Wc, const float* __restrict__ bc,
    const float* __restrict__ Wfc, const float* __restrict__ bfc,
    float* __restrict__ out)
{
    __shared__ float sm[6400];
    __shared__ int toks[B];
    const size_t HID_OFF = (size_t)B * TGT * V;
    const size_t ATTN_OFF = HID_OFF + (size_t)2 * BH;

    for (int s = 0; s < TGT; s++) {
        if (threadIdx.x < B) toks[threadIdx.x] = s ? g_tok[threadIdx.x] : 0;
        __syncthreads();
        const float* h0in = s ? (g_dh0 + (size_t)((s - 1) & 1) * BH) : (g_h0seq + (size_t)(TIN - 1) * BH);
        const float* h1in = s ? (g_dh1 + (size_t)((s - 1) & 1) * BH) : (g_enc + (size_t)(TIN - 1) * BH);
        float* h0out = g_dh0 + (size_t)(s & 1) * BH;
        float* h1out = g_dh1 + (size_t)(s & 1) * BH;

        dec_gru_phase(embed, H, toks, dWih0, dbih0, h0in, dWhh0, dbhh0, h0out, nullptr, sm);
        dec_gru_phase(h0out, H, nullptr, dWih1, dbih1, h1in, dWhh1, dbhh1, h1out, g_cat, sm);
        lin_phase(Wq, H, bq, h1out, H, H, g_q, sm);
        attn_phase(g_q, g_enc, g_cat, out + ATTN_OFF, s, sm);
        lin_phase(Wc, 2 * H, bc, g_cat, 2 * H, 2 * H, g_comb, sm);
        fc_phase(g_comb, Wfc, bfc, out, s, sm);
        argmax_phase(out, s, sm);
    }
    // final hidden [2, B, H] — decoder (h0, h1) after last step (parity of TGT-1)
    const float* f0 = g_dh0 + (size_t)((TGT - 1) & 1) * BH;
    const float* f1 = g_dh1 + (size_t)((TGT - 1) & 1) * BH;
    for (size_t i = (size_t)blockIdx.x * 256 + threadIdx.x; i < (size_t)BH;
         i += (size_t)gridDim.x * 256) {
        out[HID_OFF + i] = f0[i];
        out[HID_OFF + BH + i] = f1[i];
    }
}

// ---------------- host orchestration: 5 graph nodes ----------------
extern "C" void kernel_launch(void* const* d_in, const int* in_sizes, int n_in,
                              void* d_out_, int out_size) {
    const float* x      = (const float*)d_in[0];
    const float* embed  = (const float*)d_in[1];
    const float* eWih0  = (const float*)d_in[2];
    const float* eWhh0  = (const float*)d_in[3];
    const float* ebih0  = (const float*)d_in[4];
    const float* ebhh0  = (const float*)d_in[5];
    const float* eWih1  = (const float*)d_in[6];
    const float* eWhh1  = (const float*)d_in[7];
    const float* ebih1  = (const float*)d_in[8];
    const float* ebhh1  = (const float*)d_in[9];
    const float* dWih0  = (const float*)d_in[10];
    const float* dWhh0  = (const float*)d_in[11];
    const float* dbih0  = (const float*)d_in[12];
    const float* dbhh0  = (const float*)d_in[13];
    const float* dWih1  = (const float*)d_in[14];
    const float* dWhh1  = (const float*)d_in[15];
    const float* dbih1  = (const float*)d_in[16];
    const float* dbhh1  = (const float*)d_in[17];
    const float* Wq     = (const float*)d_in[18];
    const float* bq     = (const float*)d_in[19];
    const float* Wc     = (const float*)d_in[20];
    const float* bc     = (const float*)d_in[21];
    const float* Wfc    = (const float*)d_in[22];
    const float* bfc    = (const float*)d_in[23];
    float* out = (float*)d_out_;

    float *gi0, *gi1, *h0seq, *enc;
    cudaGetSymbolAddress((void**)&gi0,   g_gi0);
    cudaGetSymbolAddress((void**)&gi1,   g_gi1);
    cudaGetSymbolAddress((void**)&h0seq, g_h0seq);
    cudaGetSymbolAddress((void**)&enc,   g_enc);

    const int ENC_SMEM = (24 * WS_PITCH + 64 * XS_PITCH) * (int)sizeof(float);
    cudaFuncSetAttribute(enc_recur_kernel, cudaFuncAttributeMaxDynamicSharedMemorySize, ENC_SMEM);

    int dev = 0; cudaGetDevice(&dev);
    int nb = 0;
    cudaDeviceGetAttribute(&nb, cudaDevAttrMultiProcessorCount, dev);
    if (nb < 128) nb = 148;   // safety fallback

    // 1) gi0 = X @ eWih0^T + ebih0   (rows b*TIN+t, K=F)
    gemm_tn<64,128,8,4,8><<<dim3(H3/128, (B*TIN)/64), 256>>>(
        x, eWih0, ebih0, gi0, B*TIN, H3, F, F, F, H3);

    // 2) encoder layer 0 recurrence (persistent)
    enc_recur_kernel<<<128, 256, ENC_SMEM>>>(
        gi0, (long long)H3, (long long)TIN * H3, eWhh0, ebhh0, h0seq);

    // 3) gi1 = H0seq @ eWih1^T + ebih1  (rows t*B+b, K=H)
    gemm_tn<64,128,8,4,8><<<dim3(H3/128, (B*TIN)/64), 256>>>(
        h0seq, eWih1, ebih1, gi1, B*TIN, H3, H, H, H, H3);

    // 4) encoder layer 1 recurrence (persistent)
    enc_recur_kernel<<<128, 256, ENC_SMEM>>>(
        gi1, (long long)B * H3, (long long)H3, eWhh1, ebhh1, enc);

    // 5) full autoregressive decoder (persistent)
    decoder_kernel<<<nb, 256>>>(
        embed,
        dWih0, dbih0, dWhh0, dbhh0,
        dWih1, dbih1, dWhh1, dbhh1,
        Wq, bq, Wc, bc, Wfc, bfc, out);
}

// round 3
// speedup vs baseline: 1.0247x; 1.0247x over previous
#include <cuda_runtime.h>
#include <cfloat>
#include <cstddef>

#define B 64
#define TIN 256
#define F 64
#define H 1024
#define H3 3072
#define TGT 64
#define V 32000
#define BH (B*H)

// ---------------- device-global scratch (no allocation allowed) ----------------
__device__ float g_gi0[(size_t)TIN * B * H3];   // rows (b*TIN + t), 3H wide
__device__ float g_gi1[(size_t)TIN * B * H3];   // rows (t*B + b), 3H wide
__device__ float g_h0seq[(size_t)TIN * BH];     // [t][b][H]
__device__ float g_enc[(size_t)TIN * BH];       // [t][b][H]
__device__ float g_dh0[2 * BH];
__device__ float g_dh1[2 * BH];
__device__ float g_q[BH];
__device__ float g_cat[B * 2 * H];              // [b][0:H]=att, [b][H:2H]=h1
__device__ float g_comb[BH];
__device__ int   g_tok[B];
__device__ unsigned long long g_bar64;          // low32 = count, high32 = generation

__device__ __forceinline__ void grid_sync() {
    __syncthreads();
    if (threadIdx.x == 0) {
        __threadfence();
        unsigned long long old = atomicAdd(&g_bar64, 1ULL);
        unsigned gen = (unsigned)(old >> 32);
        if ((unsigned)old == gridDim.x - 1) {
            // last arriver: reset count to 0 and bump generation atomically
            atomicAdd(&g_bar64, (1ULL << 32) - (unsigned long long)gridDim.x);
        } else {
            while ((unsigned)((*(volatile unsigned long long*)&g_bar64) >> 32) == gen) { }
        }
        __threadfence();
    }
    __syncthreads();
}

__device__ __forceinline__ float sigmoidf_(float x) { return 1.f / (1.f + expf(-x)); }

// ---------------- generic GEMM: C[M,N] = A[M,K] @ W[N,K]^T + bias ----------------
template<int BM, int BN, int BK, int TM, int TN>
__global__ void gemm_tn(const float* __restrict__ A, const float* __restrict__ Wt,
                        const float* __restrict__ bias, float* __restrict__ C,
                        int M, int N, int K, int lda, int ldw, int ldc) {
    constexpr int TX = BN / TN;
    constexpr int TY = BM / TM;
    constexpr int NT = TX * TY;
    __shared__ float As[BK][BM + 1];
    __shared__ float Ws[BK][BN + 1];
    const int tid = threadIdx.x;
    const int tx = tid % TX, ty = tid / TX;
    const int m0 = blockIdx.y * BM, n0 = blockIdx.x * BN;

    float acc[TM][TN];
#pragma unroll
    for (int i = 0; i < TM; i++)
#pragma unroll
        for (int j = 0; j < TN; j++) acc[i][j] = 0.f;

    for (int k0 = 0; k0 < K; k0 += BK) {
        for (int i = tid; i < BM * BK; i += NT) {
            int m = i / BK, k = i % BK;
            As[k][m] = A[(size_t)(m0 + m) * lda + k0 + k];
        }
        for (int i = tid; i < BN * BK; i += NT) {
            int n = i / BK, k = i % BK;
            Ws[k][n] = Wt[(size_t)(n0 + n) * ldw + k0 + k];
        }
        __syncthreads();
#pragma unroll
        for (int k = 0; k < BK; k++) {
            float a[TM], w[TN];
#pragma unroll
            for (int i = 0; i < TM; i++) a[i] = As[k][ty + i * TY];
#pragma unroll
            for (int j = 0; j < TN; j++) w[j] = Ws[k][tx + j * TX];
#pragma unroll
            for (int i = 0; i < TM; i++)
#pragma unroll
                for (int j = 0; j < TN; j++) acc[i][j] = fmaf(a[i], w[j], acc[i][j]);
        }
        __syncthreads();
    }
#pragma unroll
    for (int i = 0; i < TM; i++) {
        int m = m0 + ty + i * TY;
#pragma unroll
        for (int j = 0; j < TN; j++) {
            int n = n0 + tx + j * TX;
            C[(size_t)m * ldc + n] = acc[i][j] + (bias ? bias[n] : 0.f);
        }
    }
}

// ---------------- persistent encoder recurrence (one layer, all 256 steps) ----------------
// grid = 128 blocks x 256 threads. Block owns 8 output cols; Whh slice (24 rows x 1024)
// held in smem for the whole kernel. Grid-sync per timestep.
#define WS_PITCH 1028
#define XS_PITCH 68
__global__ __launch_bounds__(256, 1) void enc_recur_kernel(
    const float* __restrict__ gi, long long gi_t_stride, long long gi_b_stride,
    const float* __restrict__ Whh, const float* __restrict__ bhh,
    float* __restrict__ hseq)
{
    extern __shared__ float sm[];
    float* ws = sm;                      // 24 x WS_PITCH
    float* xs = sm + 24 * WS_PITCH;      // 64 x XS_PITCH

    const int tid = threadIdx.x;
    const int c = tid & 7, bq = tid >> 3;
    const int jb = blockIdx.x * 8;
    const int b0 = 2 * bq, b1 = b0 + 1;
    const int j = jb + c;

    // preload Whh rows (r, z, n gates for our 8 columns), full K
    for (int i = tid; i < 24 * 256; i += 256) {
        int r = i >> 8, kg = i & 255;
        int wr = (r >> 3) * H + jb + (r & 7);
        *(float4*)(ws + r * WS_PITCH + kg * 4) =
            *(const float4*)(Whh + (size_t)wr * H + kg * 4);
    }
    const float br = bhh[j], bz = bhh[H + j], bn = bhh[2 * H + j];
    __syncthreads();

    for (int t = 0; t < TIN; t++) {
        float ar0 = 0.f, ar1 = 0.f, az0 = 0.f, az1 = 0.f, an0 = 0.f, an1 = 0.f;
        const float* hprev = hseq + (size_t)(t - 1) * BH;
        if (t > 0) {
            for (int k0 = 0; k0 < H; k0 += 64) {
                for (int i = tid; i < 1024; i += 256) {
                    int b = i >> 4, kg = i & 15;
                    *(float4*)(xs + b * XS_PITCH + kg * 4) =
                        *(const float4*)(hprev + (size_t)b * H + k0 + kg * 4);
                }
                __syncthreads();
#pragma unroll
                for (int kk = 0; kk < 64; kk += 4) {
                    float4 x0 = *(const float4*)(xs + b0 * XS_PITCH + kk);
                    float4 x1 = *(const float4*)(xs + b1 * XS_PITCH + kk);
                    float4 w0 = *(const float4*)(ws + c * WS_PITCH + k0 + kk);
                    float4 w1 = *(const float4*)(ws + (8 + c) * WS_PITCH + k0 + kk);
                    float4 w2 = *(const float4*)(ws + (16 + c) * WS_PITCH + k0 + kk);
                    ar0 = fmaf(w0.x, x0.x, ar0); ar0 = fmaf(w0.y, x0.y, ar0);
                    ar0 = fmaf(w0.z, x0.z, ar0); ar0 = fmaf(w0.w, x0.w, ar0);
                    ar1 = fmaf(w0.x, x1.x, ar1); ar1 = fmaf(w0.y, x1.y, ar1);
                    ar1 = fmaf(w0.z, x1.z, ar1); ar1 = fmaf(w0.w, x1.w, ar1);
                    az0 = fmaf(w1.x, x0.x, az0); az0 = fmaf(w1.y, x0.y, az0);
                    az0 = fmaf(w1.z, x0.z, az0); az0 = fmaf(w1.w, x0.w, az0);
                    az1 = fmaf(w1.x, x1.x, az1); az1 = fmaf(w1.y, x1.y, az1);
                    az1 = fmaf(w1.z, x1.z, az1); az1 = fmaf(w1.w, x1.w, az1);
                    an0 = fmaf(w2.x, x0.x, an0); an0 = fmaf(w2.y, x0.y, an0);
                    an0 = fmaf(w2.z, x0.z, an0); an0 = fmaf(w2.w, x0.w, an0);
                    an1 = fmaf(w2.x, x1.x, an1); an1 = fmaf(w2.y, x1.y, an1);
                    an1 = fmaf(w2.z, x1.z, an1); an1 = fmaf(w2.w, x1.w, an1);
                }
                __syncthreads();
            }
        }
        // epilogue
        const float* gr0 = gi + (size_t)b0 * gi_b_stride + (size_t)t * gi_t_stride;
        const float* gr1 = gi + (size_t)b1 * gi_b_stride + (size_t)t * gi_t_stride;
        float* hout = hseq + (size_t)t * BH;
        float hp0 = (t > 0) ? hprev[(size_t)b0 * H + j] : 0.f;
        float hp1 = (t > 0) ? hprev[(size_t)b1 * H + j] : 0.f;
        {
            float r = sigmoidf_(gr0[j] + ar0 + br);
            float z = sigmoidf_(gr0[H + j] + az0 + bz);
            float n = tanhf(gr0[2 * H + j] + r * (an0 + bn));
            hout[(size_t)b0 * H + j] = (1.f - z) * n + z * hp0;
        }
        {
            float r = sigmoidf_(gr1[j] + ar1 + br);
            float z = sigmoidf_(gr1[H + j] + az1 + bz);
            float n = tanhf(gr1[2 * H + j] + r * (an1 + bn));
            hout[(size_t)b1 * H + j] = (1.f - z) * n + z * hp1;
        }
        grid_sync();
    }
}

// ---------------- decoder building block: block-level GEMM accumulate ----------------
// acc[g*2+u] += sum_k W[((g*H)+jb+c)*wstride + k] * X[row(b_u)][k]
template<int NG>
__device__ __forceinline__ void block_mm(
    const float* __restrict__ W, int wstride,
    const float* __restrict__ X, int xstride, const int* __restrict__ rowidx,
    int K, float* acc, float* sm)
{
    const int tid = threadIdx.x;
    const int c = tid & 7, bq = tid >> 3;
    const int jb = blockIdx.x * 8;
    const int b0 = 2 * bq, b1 = b0 + 1;
    float* ws = sm;                     // NG*8 x XS_PITCH
    float* xs = sm + NG * 8 * XS_PITCH; // 64 x XS_PITCH

    for (int k0 = 0; k0 < K; k0 += 64) {
        for (int i = tid; i < 1024; i += 256) {
            int b = i >> 4, kg = i & 15;
            int xr = rowidx ? rowidx[b] : b;
            *(float4*)(xs + b * XS_PITCH + kg * 4) =
                *(const float4*)(X + (size_t)xr * xstride + k0 + kg * 4);
        }
        for (int i = tid; i < NG * 8 * 16; i += 256) {
            int r = i >> 4, kg = i & 15;
            int wr = (r >> 3) * H + jb + (r & 7);
            *(float4*)(ws + r * XS_PITCH + kg * 4) =
                *(const float4*)(W + (size_t)wr * wstride + k0 + kg * 4);
        }
        __syncthreads();
#pragma unroll
        for (int kk = 0; kk < 64; kk += 4) {
            float4 x0 = *(const float4*)(xs + b0 * XS_PITCH + kk);
            float4 x1 = *(const float4*)(xs + b1 * XS_PITCH + kk);
#pragma unroll
            for (int g = 0; g < NG; g++) {
                float4 w = *(const float4*)(ws + (g * 8 + c) * XS_PITCH + kk);
                float a0 = acc[g * 2], a1 = acc[g * 2 + 1];
                a0 = fmaf(w.x, x0.x, a0); a0 = fmaf(w.y, x0.y, a0);
                a0 = fmaf(w.z, x0.z, a0); a0 = fmaf(w.w, x0.w, a0);
                a1 = fmaf(w.x, x1.x, a1); a1 = fmaf(w.y, x1.y, a1);
                a1 = fmaf(w.z, x1.z, a1); a1 = fmaf(w.w, x1.w, a1);
                acc[g * 2] = a0; acc[g * 2 + 1] = a1;
            }
        }
        __syncthreads();
    }
}

__device__ __forceinline__ void dec_gru_phase(
    const float* __restrict__ x, int xstride, const int* __restrict__ rowidx,
    const float* __restrict__ Wih, const float* __restrict__ bih,
    const float* __restrict__ hin,
    const float* __restrict__ Whh, const float* __restrict__ bhh,
    float* __restrict__ hout, float* __restrict__ cat_aux, float* sm)
{
    if (blockIdx.x < 128) {
        float ai[6] = {0,0,0,0,0,0}, ah[6] = {0,0,0,0,0,0};
        block_mm<3>(Wih, H, x, xstride, rowidx, H, ai, sm);
        block_mm<3>(Whh, H, hin, H, nullptr, H, ah, sm);
        const int tid = threadIdx.x, c = tid & 7, bq = tid >> 3;
        const int j = blockIdx.x * 8 + c;
        const float bir = bih[j], biz = bih[H + j], bin = bih[2 * H + j];
        const float bhr = bhh[j], bhz = bhh[H + j], bhn = bhh[2 * H + j];
#pragma unroll
        for (int u = 0; u < 2; u++) {
            int b = 2 * bq + u;
            float hp = hin[(size_t)b * H + j];
            float r = sigmoidf_((ai[u] + bir) + (ah[u] + bhr));
            float z = sigmoidf_((ai[2 + u] + biz) + (ah[2 + u] + bhz));
            float n = tanhf((ai[4 + u] + bin) + r * (ah[4 + u] + bhn));
            float h = (1.f - z) * n + z * hp;
            hout[(size_t)b * H + j] = h;
            if (cat_aux) cat_aux[(size_t)b * 2 * H + H + j] = h;
        }
    }
    grid_sync();
}

__device__ __forceinline__ void lin_phase(
    const float* __restrict__ Wt, int wstride, const float* __restrict__ bias,
    const float* __restrict__ X, int xstride, int K, float* __restrict__ Y, float* sm)
{
    if (blockIdx.x < 128) {
        float a[2] = {0, 0};
        block_mm<1>(Wt, wstride, X, xstride, nullptr, K, a, sm);
        const int tid = threadIdx.x, c = tid & 7, bq = tid >> 3;
        const int j = blockIdx.x * 8 + c;
#pragma unroll
        for (int u = 0; u < 2; u++) {
            int b = 2 * bq + u;
            Y[(size_t)b * H + j] = a[u] + bias[j];
        }
    }
    grid_sync();
}

__device__ __forceinline__ void attn_phase(
    const float* __restrict__ q, const float* __restrict__ enc,
    float* __restrict__ cat, float* __restrict__ attn_out, int s, float* sm)
{
    if (blockIdx.x < B) {
        const int b = blockIdx.x, tid = threadIdx.x;
        float* qs = sm;           // 1024
        float* wv = sm + 1024;    // 256
        float* red = sm + 1280;   // 256
        for (int i = tid; i < H; i += 256) qs[i] = q[(size_t)b * H + i];
        __syncthreads();
        const int warp = tid >> 5, lane = tid & 31;
        for (int t = warp; t < TIN; t += 8) {
            const float* e = enc + (size_t)(t * B + b) * H;
            float sacc = 0.f;
#pragma unroll 4
            for (int k = lane; k < H; k += 32) sacc = fmaf(qs[k], e[k], sacc);
            for (int o = 16; o; o >>= 1) sacc += __shfl_xor_sync(0xffffffffu, sacc, o);
            if (!lane) wv[t] = sacc;
        }
        __syncthreads();
        float v = wv[tid];
        red[tid] = v; __syncthreads();
        for (int st = 128; st; st >>= 1) { if (tid < st) red[tid] = fmaxf(red[tid], red[tid + st]); __syncthreads(); }
        float mx = red[0]; __syncthreads();
        float ev = expf(v - mx);
        red[tid] = ev; __syncthreads();
        for (int st = 128; st; st >>= 1) { if (tid < st) red[tid] += red[tid + st]; __syncthreads(); }
        float aw = ev / red[0];
        wv[tid] = aw;
        attn_out[((size_t)b * TIN + tid) * TGT + s] = aw;
        __syncthreads();
#pragma unroll
        for (int kk = 0; kk < 4; kk++) {
            int k = tid + kk * 256;
            float sacc = 0.f;
            for (int t = 0; t < TIN; t++) sacc = fmaf(wv[t], enc[(size_t)(t * B + b) * H + k], sacc);
            cat[(size_t)b * 2 * H + k] = sacc;
        }
    }
    grid_sync();
}

__device__ __forceinline__ void fc_phase(
    const float* __restrict__ A, const float* __restrict__ Wfc,
    const float* __restrict__ bfc, float* __restrict__ out, int s, float* sm)
{
    float* As = sm;             // 32 x 65
    float* Ws2 = sm + 32 * 65;  // 32 x 130
    const int tid = threadIdx.x;
    const int tx = tid & 15, ty = tid >> 4;
    for (int tile = blockIdx.x; tile < V / 128; tile += gridDim.x) {
        const int n0 = tile * 128;
        float acc[4][8];
#pragma unroll
        for (int i = 0; i < 4; i++)
#pragma unroll
            for (int jj = 0; jj < 8; jj++) acc[i][jj] = 0.f;
        for (int k0 = 0; k0 < H; k0 += 32) {
            for (int i = tid; i < 64 * 32; i += 256) {
                int m = i >> 5, k = i & 31;
                As[k * 65 + m] = A[(size_t)m * H + k0 + k];
            }
            for (int i = tid; i < 128 * 32; i += 256) {
                int n = i >> 5, k = i & 31;
                Ws2[k * 130 + n] = Wfc[(size_t)(n0 + n) * H + k0 + k];
            }
            __syncthreads();
#pragma unroll
            for (int k = 0; k < 32; k++) {
                float av[4], wv2[8];
#pragma unroll
                for (int i = 0; i < 4; i++) av[i] = As[k * 65 + ty + i * 16];
#pragma unroll
                for (int jj = 0; jj < 8; jj++) wv2[jj] = Ws2[k * 130 + tx + jj * 16];
#pragma unroll
                for (int i = 0; i < 4; i++)
#pragma unroll
                    for (int jj = 0; jj < 8; jj++) acc[i][jj] = fmaf(av[i], wv2[jj], acc[i][jj]);
            }
            __syncthreads();
        }
#pragma unroll
        for (int i = 0; i < 4; i++) {
            int m = ty + i * 16;
#pragma unroll
            for (int jj = 0; jj < 8; jj++) {
                int n = n0 + tx + jj * 16;
                out[((size_t)m * TGT + s) * V + n] = acc[i][jj] + bfc[n];
            }
        }
    }
    grid_sync();
}

__device__ __forceinline__ void argmax_phase(const float* __restrict__ out, int s, float* sm)
{
    if (blockIdx.x < B) {
        const int b = blockIdx.x, tid = threadIdx.x;
        const float* row = out + ((size_t)b * TGT + s) * V;
        float best = -FLT_MAX; int bi = 0;
        for (int i = tid; i < V; i += 256) {
            float x = row[i];
            if (x > best) { best = x; bi = i; }
        }
        float* sv = sm;
        int* si = (int*)(sm + 256);
        sv[tid] = best; si[tid] = bi; __syncthreads();
        for (int st = 128; st; st >>= 1) {
            if (tid < st) {
                if (sv[tid + st] > sv[tid] ||
                    (sv[tid + st] == sv[tid] && si[tid + st] < si[tid])) {
                    sv[tid] = sv[tid + st]; si[tid] = si[tid + st];
                }
            }
            __syncthreads();
        }
        if (!tid) g_tok[b] = si[0];
    }
    grid_sync();
}

// ---------------- persistent decoder: all 64 steps in one kernel ----------------
__global__ __launch_bounds__(256, 1) void decoder_kernel(
    const float* __restrict__ embed,
    const float* __restrict__ dWih0, const float* __restrict__ dbih0,
    const float* __restrict__ dWhh0, const float* __restrict__ dbhh0,
    const float* __restrict__ dWih1, const float* __restrict__ dbih1,
    const float* __restrict__ dWhh1, const float* __restrict__ dbhh1,
    const float* __restrict__ Wq, const float* __restrict__ bq,
    const float* __restrict__ Wc, const float* __restrict__ bc,
    const float* __restrict__ Wfc, const float* __restrict__ bfc,
    float* __restrict__ out)
{
    __shared__ float sm[6400];
    __shared__ int toks[B];
    const size_t HID_OFF = (size_t)B * TGT * V;
    const size_t ATTN_OFF = HID_OFF + (size_t)2 * BH;

    for (int s = 0; s < TGT; s++) {
        if (threadIdx.x < B) toks[threadIdx.x] = s ? g_tok[threadIdx.x] : 0;
        __syncthreads();
        const float* h0in = s ? (g_dh0 + (size_t)((s - 1) & 1) * BH) : (g_h0seq + (size_t)(TIN - 1) * BH);
        const float* h1in = s ? (g_dh1 + (size_t)((s - 1) & 1) * BH) : (g_enc + (size_t)(TIN - 1) * BH);
        float* h0out = g_dh0 + (size_t)(s & 1) * BH;
        float* h1out = g_dh1 + (size_t)(s & 1) * BH;

        dec_gru_phase(embed, H, toks, dWih0, dbih0, h0in, dWhh0, dbhh0, h0out, nullptr, sm);
        dec_gru_phase(h0out, H, nullptr, dWih1, dbih1, h1in, dWhh1, dbhh1, h1out, g_cat, sm);
        lin_phase(Wq, H, bq, h1out, H, H, g_q, sm);
        attn_phase(g_q, g_enc, g_cat, out + ATTN_OFF, s, sm);
        lin_phase(Wc, 2 * H, bc, g_cat, 2 * H, 2 * H, g_comb, sm);
        fc_phase(g_comb, Wfc, bfc, out, s, sm);
        argmax_phase(out, s, sm);
    }
    // final hidden [2, B, H] — decoder (h0, h1) after last step (parity of TGT-1)
    const float* f0 = g_dh0 + (size_t)((TGT - 1) & 1) * BH;
    const float* f1 = g_dh1 + (size_t)((TGT - 1) & 1) * BH;
    for (size_t i = (size_t)blockIdx.x * 256 + threadIdx.x; i < (size_t)BH;
         i += (size_t)gridDim.x * 256) {
        out[HID_OFF + i] = f0[i];
        out[HID_OFF + BH + i] = f1[i];
    }
}

// ---------------- host orchestration: 5 graph nodes ----------------
extern "C" void kernel_launch(void* const* d_in, const int* in_sizes, int n_in,
                              void* d_out_, int out_size) {
    const float* x      = (const float*)d_in[0];
    const float* embed  = (const float*)d_in[1];
    const float* eWih0  = (const float*)d_in[2];
    const float* eWhh0  = (const float*)d_in[3];
    const float* ebih0  = (const float*)d_in[4];
    const float* ebhh0  = (const float*)d_in[5];
    const float* eWih1  = (const float*)d_in[6];
    const float* eWhh1  = (const float*)d_in[7];
    const float* ebih1  = (const float*)d_in[8];
    const float* ebhh1  = (const float*)d_in[9];
    const float* dWih0  = (const float*)d_in[10];
    const float* dWhh0  = (const float*)d_in[11];
    const float* dbih0  = (const float*)d_in[12];
    const float* dbhh0  = (const float*)d_in[13];
    const float* dWih1  = (const float*)d_in[14];
    const float* dWhh1  = (const float*)d_in[15];
    const float* dbih1  = (const float*)d_in[16];
    const float* dbhh1  = (const float*)d_in[17];
    const float* Wq     = (const float*)d_in[18];
    const float* bq     = (const float*)d_in[19];
    const float* Wc     = (const float*)d_in[20];
    const float* bc     = (const float*)d_in[21];
    const float* Wfc    = (const float*)d_in[22];
    const float* bfc    = (const float*)d_in[23];
    float* out = (float*)d_out_;

    float *gi0, *gi1, *h0seq, *enc;
    cudaGetSymbolAddress((void**)&gi0,   g_gi0);
    cudaGetSymbolAddress((void**)&gi1,   g_gi1);
    cudaGetSymbolAddress((void**)&h0seq, g_h0seq);
    cudaGetSymbolAddress((void**)&enc,   g_enc);

    const int ENC_SMEM = (24 * WS_PITCH + 64 * XS_PITCH) * (int)sizeof(float);
    cudaFuncSetAttribute(enc_recur_kernel, cudaFuncAttributeMaxDynamicSharedMemorySize, ENC_SMEM);

    int dev = 0; cudaGetDevice(&dev);
    int nb = 0;
    cudaDeviceGetAttribute(&nb, cudaDevAttrMultiProcessorCount, dev);
    if (nb < 128) nb = 148;   // safety fallback

    // 1) gi0 = X @ eWih0^T + ebih0   (rows b*TIN+t, K=F)
    gemm_tn<64,128,8,4,8><<<dim3(H3/128, (B*TIN)/64), 256>>>(
        x, eWih0, ebih0, gi0, B*TIN, H3, F, F, F, H3);

    // 2) encoder layer 0 recurrence (persistent)
    enc_recur_kernel<<<128, 256, ENC_SMEM>>>(
        gi0, (long long)H3, (long long)TIN * H3, eWhh0, ebhh0, h0seq);

    // 3) gi1 = H0seq @ eWih1^T + ebih1  (rows t*B+b, K=H)
    gemm_tn<64,128,8,4,8><<<dim3(H3/128, (B*TIN)/64), 256>>>(
        h0seq, eWih1, ebih1, gi1, B*TIN, H3, H, H, H, H3);

    // 4) encoder layer 1 recurrence (persistent)
    enc_recur_kernel<<<128, 256, ENC_SMEM>>>(
        gi1, (long long)B * H3, (long long)H3, eWhh1, ebhh1, enc);

    // 5) full autoregressive decoder (persistent)
    decoder_kernel<<<nb, 256>>>(
        embed,
        dWih0, dbih0, dWhh0, dbhh0,
        dWih1, dbih1, dWhh1, dbhh1,
        Wq, bq, Wc, bc, Wfc, bfc, out);
}